// round 16
// baseline (speedup 1.0000x reference)
#include <cuda_runtime.h>
#include <cuda_bf16.h>
#include <stdint.h>

#define BB 8192
#define DD 2048
#define KK 512
#define QQ 8
#define CC (KK*QQ)

// mma.sync GEMM tiling (sm_103 legacy tensor path; tcgen05 NOT available in toolchain)
#define BM 256              // samples per CTA
#define BN 128              // 16 components x q=8
#define BKc 32              // K elems per stage
#define NKI (DD/BKc)        // 64 k-iterations
#define NKT (CC/BN)         // 32 component-tiles
#define ROWB 80             // smem row stride bytes (40 bf16; pad -> LDSM conflict-free)
#define STG_SZ (400*ROWB)   // A(256 rows)+B(128)+MU(16) = 400 rows -> 32000 B
#define SMEM_DYN 104448

// epilogue smem layout (bytes, reusing stage area after mainloop)
#define EP_STGW 9216        // per-warp slot: 64 rows x 36 floats
#define EP_MU   73728       // 256 x 17 floats
#define EP_L    91136       // 16 x 64 floats
#define EP_VMU  95232       // 128 floats
#define EP_C2   95744       // 16 floats
#define EP_M    95808       // 4 x 256 floats
#define EP_S    99904       // 4 x 256 floats

// ---------------- scratch (static device globals; no allocation) -------------
__device__ __nv_bfloat16 g_Xbf[(size_t)BB*DD];      // 32 MB
__device__ __nv_bfloat16 g_PW[(size_t)CC*DD];       // 16 MB  psi_inv * W
__device__ __nv_bfloat16 g_MuP[(size_t)KK*DD];      // 2 MB   psi_inv * mu
__device__ float g_psi_inv[DD];
__device__ float g_xpx[BB];
__device__ float g_pm[(size_t)NKT*BB];
__device__ float g_ps[(size_t)NKT*BB];
__device__ float g_L[KK*64];                        // lower-tri, diag = 1/L_ii
__device__ float g_vmu[KK*QQ];
__device__ float g_c2[KK];
__device__ float g_logdet_psi;
__device__ float g_logpi[KK];
__device__ float g_nlogp[BB];

// ---------------- helpers ----------------------------------------------------
__device__ __forceinline__ float softplus_f(float x){
  return (x > 15.f) ? x : log1pf(expf(x));
}
__device__ __forceinline__ float wredsum(float v){
  #pragma unroll
  for (int o=16;o;o>>=1) v += __shfl_down_sync(0xffffffffu, v, o);
  return v;
}
__device__ __forceinline__ void cpasync16(uint32_t s, const void* g){
  asm volatile("cp.async.cg.shared.global [%0], [%1], 16;\n" :: "r"(s), "l"(g));
}
#define LDSM4(r, addr) \
  asm volatile("ldmatrix.sync.aligned.m8n8.x4.shared.b16 {%0,%1,%2,%3}, [%4];" \
    : "=r"((r)[0]),"=r"((r)[1]),"=r"((r)[2]),"=r"((r)[3]) : "r"(addr))
#define LDSM2(r, addr) \
  asm volatile("ldmatrix.sync.aligned.m8n8.x2.shared.b16 {%0,%1}, [%2];" \
    : "=r"((r)[0]),"=r"((r)[1]) : "r"(addr))
#define MMA16816(d, a, b0, b1) \
  asm volatile("mma.sync.aligned.m16n8k16.row.col.f32.bf16.bf16.f32 " \
    "{%0,%1,%2,%3}, {%4,%5,%6,%7}, {%8,%9}, {%0,%1,%2,%3};" \
    : "+f"((d)[0]),"+f"((d)[1]),"+f"((d)[2]),"+f"((d)[3]) \
    : "r"((a)[0]),"r"((a)[1]),"r"((a)[2]),"r"((a)[3]), "r"(b0),"r"(b1))

// ---------------- small prep kernels -----------------------------------------
__global__ void k_psi(const float* __restrict__ psi_rho){
  __shared__ float sh[8];
  int t = threadIdx.x;
  float acc = 0.f;
  for (int i=t;i<DD;i+=256){
    float p = softplus_f(psi_rho[i]) + 1e-5f;
    g_psi_inv[i] = 1.f/p;
    acc += logf(p);
  }
  acc = wredsum(acc);
  if ((t&31)==0) sh[t>>5] = acc;
  __syncthreads();
  if (t==0){ float s=0.f; for (int i=0;i<8;i++) s+=sh[i]; g_logdet_psi = s; }
}

__global__ void k_logpi(const float* __restrict__ pl){
  __shared__ float sh[16];
  __shared__ float s_m, s_l;
  int t = threadIdx.x;                 // 512 threads
  float v = pl[t];
  float m = v;
  #pragma unroll
  for (int o=16;o;o>>=1) m = fmaxf(m, __shfl_down_sync(0xffffffffu,m,o));
  if ((t&31)==0) sh[t>>5]=m;
  __syncthreads();
  if (t==0){ float mm=sh[0]; for(int i=1;i<16;i++) mm=fmaxf(mm,sh[i]); s_m=mm; }
  __syncthreads();
  float e = expf(v - s_m);
  float s = wredsum(e);
  if ((t&31)==0) sh[t>>5]=s;
  __syncthreads();
  if (t==0){ float ss=0.f; for(int i=0;i<16;i++) ss+=sh[i]; s_l = logf(ss); }
  __syncthreads();
  g_logpi[t] = v - s_m - s_l;
}

__global__ void __launch_bounds__(256) k_prepx(const float* __restrict__ x){
  __shared__ float sh[8];
  int b = blockIdx.x, t = threadIdx.x;
  const float4* __restrict__ xr = (const float4*)(x + (size_t)b*DD);
  uint2* xo = (uint2*)(g_Xbf + (size_t)b*DD);
  const float4* pv = (const float4*)g_psi_inv;
  float acc=0.f;
  for (int j=t;j<DD/4;j+=256){
    float4 xv = xr[j];
    float4 pi = pv[j];
    uint2 o;
    __nv_bfloat162 lo = __floats2bfloat162_rn(xv.x, xv.y);
    __nv_bfloat162 hi = __floats2bfloat162_rn(xv.z, xv.w);
    o.x = *(uint32_t*)&lo; o.y = *(uint32_t*)&hi;
    xo[j] = o;
    acc = fmaf(xv.x*xv.x, pi.x, acc);
    acc = fmaf(xv.y*xv.y, pi.y, acc);
    acc = fmaf(xv.z*xv.z, pi.z, acc);
    acc = fmaf(xv.w*xv.w, pi.w, acc);
  }
  acc = wredsum(acc);
  if ((t&31)==0) sh[t>>5]=acc;
  __syncthreads();
  if (t==0){ float s=0.f; for(int i=0;i<8;i++) s+=sh[i]; g_xpx[b]=s; }
}

#define TRI(i,j) ((i)*8+(j)-(((i)*((i)+1))>>1))
__global__ void __launch_bounds__(256) k_prepk(const float* __restrict__ mu,
     const float* __restrict__ dir_raw, const float* __restrict__ scale_rho){
  __shared__ __nv_bfloat16 s_pw[DD*QQ];
  __shared__ __nv_bfloat16 s_pm[DD];
  __shared__ float s_part[8][56];
  __shared__ float s_red[56];
  __shared__ float s_ws[8];
  int k = blockIdx.x, t = threadIdx.x, lane=t&31, w=t>>5;
  const float* __restrict__ dr  = dir_raw + (size_t)k*DD*QQ;
  const float* __restrict__ mur = mu + (size_t)k*DD;
  float gq[36], nsq[8], vm[8]; float mpm=0.f;
  #pragma unroll
  for (int i=0;i<36;i++) gq[i]=0.f;
  #pragma unroll
  for (int i=0;i<8;i++){ nsq[i]=0.f; vm[i]=0.f; }
  for (int d=t; d<DD; d+=256){
    float4 p0 = *(const float4*)(dr + (size_t)d*8);
    float4 p1 = *(const float4*)(dr + (size_t)d*8 + 4);
    float w8[8] = {p0.x,p0.y,p0.z,p0.w,p1.x,p1.y,p1.z,p1.w};
    float pinv = g_psi_inv[d];
    float md = mur[d];
    mpm = fmaf(md*md, pinv, mpm);
    float mp = md*pinv;
    s_pm[d] = __float2bfloat16(mp);
    float pw8[8];
    #pragma unroll
    for (int q=0;q<8;q++){
      nsq[q] = fmaf(w8[q],w8[q],nsq[q]);
      vm[q]  = fmaf(mp,w8[q],vm[q]);
      pw8[q] = pinv*w8[q];
      s_pw[d*8+q] = __float2bfloat16(pw8[q]);
    }
    #pragma unroll
    for (int i=0;i<8;i++){
      #pragma unroll
      for (int j=i;j<8;j++) gq[TRI(i,j)] = fmaf(pw8[i], w8[j], gq[TRI(i,j)]);
    }
  }
  #pragma unroll
  for (int i=0;i<36;i++){ float r = wredsum(gq[i]);  if(lane==0) s_part[w][i]=r; }
  #pragma unroll
  for (int q=0;q<8;q++){ float r = wredsum(nsq[q]); if(lane==0) s_part[w][36+q]=r; }
  #pragma unroll
  for (int q=0;q<8;q++){ float r = wredsum(vm[q]);  if(lane==0) s_part[w][44+q]=r; }
  { float r = wredsum(mpm); if(lane==0) s_part[w][52]=r; }
  __syncthreads();
  if (t<53){ float s=0.f; for(int wi=0;wi<8;wi++) s+=s_part[wi][t]; s_red[t]=s; }
  __syncthreads();
  if (t<8){
    float n = fmaxf(sqrtf(s_red[36+t]), 1e-5f);
    s_ws[t] = softplus_f(scale_rho[k*8+t]) / n;
  }
  __syncthreads();
  if (t<8) g_vmu[k*8+t] = s_ws[t]*s_red[44+t];
  if (t==0){
    float Mm[8][8], Lm[8][8], inv[8]; float ld=0.f;
    #pragma unroll
    for (int i=0;i<8;i++){
      #pragma unroll
      for (int j=i;j<8;j++){
        float m = s_ws[i]*s_ws[j]*s_red[TRI(i,j)] + ((i==j)?1.f:0.f);
        Mm[i][j]=m; Mm[j][i]=m;
      }
    }
    for (int i=0;i<8;i++){
      float s = Mm[i][i];
      for (int p=0;p<i;p++) s -= Lm[i][p]*Lm[i][p];
      float lii = sqrtf(s);
      ld += 2.f*logf(lii);
      inv[i] = 1.f/lii;
      Lm[i][i] = lii;
      for (int j=i+1;j<8;j++){
        float v2 = Mm[j][i];
        for (int p=0;p<i;p++) v2 -= Lm[j][p]*Lm[i][p];
        Lm[j][i] = v2*inv[i];
      }
    }
    for (int i=0;i<8;i++)
      for (int j=0;j<8;j++)
        g_L[k*64+i*8+j] = (i==j) ? inv[i] : (j<i ? Lm[i][j] : 0.f);
    g_c2[k] = -0.5f*((float)DD*1.8378770664093453f + g_logdet_psi + ld + s_red[52])
              + g_logpi[k];
  }
  __syncthreads();
  float ws[8];
  #pragma unroll
  for (int q=0;q<8;q++) ws[q] = s_ws[q];
  for (int d=t; d<DD; d+=256){
    #pragma unroll
    for (int q=0;q<8;q++){
      float pw = __bfloat162float(s_pw[d*8+q]);
      g_PW[(size_t)(k*8+q)*DD + d] = __float2bfloat16(pw*ws[q]);
    }
    g_MuP[(size_t)k*DD + d] = s_pm[d];
  }
}

// ---------------- fused GEMM (ldmatrix + mma.sync): V + cross + solve + lse --
// CTA: 256 samples x 128 cols (16 comps) ; 16 warps, warp tile 64x32 (4 comps).
// Mu-cross split by K-parity across warp-column pairs; summed in smem epilogue.
__global__ void __launch_bounds__(512,1) k_gemm(){
  extern __shared__ __align__(16) char dsm[];
  uint32_t sb = (uint32_t)__cvta_generic_to_shared(dsm);
  int t = threadIdx.x, w = t>>5, lane = t&31;
  int wm_i = w>>2, wn_i = w&3;
  int wm = wm_i*64;                 // local row base (0..192)
  int m0 = blockIdx.x*BM;
  int n0 = blockIdx.y*BN;
  int k0 = blockIdx.y*16;

  auto load_stage = [&](int st, int kt){
    uint32_t base = sb + st*STG_SZ;
    int kc = kt*BKc;
    for (int c = t; c < 1600; c += 512){
      int r = c>>2, seg = c&3;
      const __nv_bfloat16* gp;
      if (r < 256)      gp = g_Xbf + (size_t)(m0+r)*DD;
      else if (r < 384) gp = g_PW  + (size_t)(n0+r-256)*DD;
      else              gp = g_MuP + (size_t)(k0+r-384)*DD;
      cpasync16(base + (uint32_t)r*ROWB + seg*16, gp + kc + seg*8);
    }
  };

  float acc[4][4][4];
  float accm[4][4];
  #pragma unroll
  for (int mi=0;mi<4;mi++){
    #pragma unroll
    for (int ni=0;ni<4;ni++){
      #pragma unroll
      for (int c=0;c<4;c++) acc[mi][ni][c]=0.f;
      accm[mi][ni]=0.f;
    }
  }

  load_stage(0,0); asm volatile("cp.async.commit_group;\n" ::: "memory");
  load_stage(1,1); asm volatile("cp.async.commit_group;\n" ::: "memory");

  int muks = wn_i>>1;               // which ks-parity this warp's mu MMA covers
  uint32_t mublk = (wn_i&1)<<3;     // mu n8 block row offset

  for (int kt=0; kt<NKI; kt++){
    if (kt == NKI-1) asm volatile("cp.async.wait_group 0;\n" ::: "memory");
    else             asm volatile("cp.async.wait_group 1;\n" ::: "memory");
    __syncthreads();
    if (kt+2 < NKI){
      load_stage((kt+2)%3, kt+2);
      asm volatile("cp.async.commit_group;\n" ::: "memory");
    }
    uint32_t base = sb + (uint32_t)(kt%3)*STG_SZ;
    #pragma unroll
    for (int ks=0; ks<2; ks++){
      uint32_t bq[2][4];
      #pragma unroll
      for (int p=0;p<2;p++){
        uint32_t addr = base
          + (uint32_t)(256 + wn_i*32 + p*16 + (lane&7) + ((lane>>4)<<3))*ROWB
          + (uint32_t)(ks*32 + ((lane>>3)&1)*16);
        LDSM4(bq[p], addr);
      }
      uint32_t mf[2];
      {
        uint32_t addr = base + (uint32_t)(384 + mublk + (lane&7))*ROWB
                      + (uint32_t)(ks*32 + ((lane>>3)&1)*16);
        LDSM2(mf, addr);
      }
      #pragma unroll
      for (int mi=0;mi<4;mi++){
        uint32_t a[4];
        uint32_t addr = base + (uint32_t)(wm + mi*16 + (lane&15))*ROWB
                      + (uint32_t)(ks*32 + ((lane>>4)<<4));
        LDSM4(a, addr);
        #pragma unroll
        for (int p=0;p<2;p++){
          MMA16816(acc[mi][2*p],   a, bq[p][0], bq[p][1]);
          MMA16816(acc[mi][2*p+1], a, bq[p][2], bq[p][3]);
        }
        if (ks == muks) MMA16816(accm[mi], a, mf[0], mf[1]);
      }
    }
  }
  __syncthreads();   // all MMA reads of smem done -> safe to reuse for epilogue

  float* stg  = (float*)(dsm + (size_t)(w&7)*EP_STGW);
  float* sMu  = (float*)(dsm + EP_MU);
  float* sL   = (float*)(dsm + EP_L);
  float* sVmu = (float*)(dsm + EP_VMU);
  float* sC2  = (float*)(dsm + EP_C2);
  float* sM   = (float*)(dsm + EP_M);
  float* sS   = (float*)(dsm + EP_S);
  int g = lane>>2, tg = lane&3;

  for (int i=t;i<1024;i+=512) sL[i] = g_L[(size_t)(k0+(i>>6))*64 + (i&63)];
  if (t<128) sVmu[t] = g_vmu[k0*8+t];
  if (t<16)  sC2[t]  = g_c2[k0+t];
  __syncthreads();

  #pragma unroll
  for (int round=0; round<2; round++){
    bool act = (w>>3) == round;
    if (act){
      #pragma unroll
      for (int mi=0;mi<4;mi++){
        #pragma unroll
        for (int ni=0;ni<4;ni++){
          int r = mi*16 + g, c = ni*8 + 2*tg;
          stg[r*36+c]        = acc[mi][ni][0];
          stg[r*36+c+1]      = acc[mi][ni][1];
          stg[(r+8)*36+c]    = acc[mi][ni][2];
          stg[(r+8)*36+c+1]  = acc[mi][ni][3];
        }
      }
      if (wn_i < 2){
        #pragma unroll
        for (int mi=0;mi<4;mi++){
          int r = wm + mi*16 + g, cb = (int)mublk + 2*tg;
          sMu[r*17+cb]       = accm[mi][0];
          sMu[r*17+cb+1]     = accm[mi][1];
          sMu[(r+8)*17+cb]   = accm[mi][2];
          sMu[(r+8)*17+cb+1] = accm[mi][3];
        }
      }
    }
    __syncthreads();
    if (act && wn_i >= 2){
      #pragma unroll
      for (int mi=0;mi<4;mi++){
        int r = wm + mi*16 + g, cb = (int)mublk + 2*tg;
        sMu[r*17+cb]       += accm[mi][0];
        sMu[r*17+cb+1]     += accm[mi][1];
        sMu[(r+8)*17+cb]   += accm[mi][2];
        sMu[(r+8)*17+cb+1] += accm[mi][3];
      }
    }
    __syncthreads();
    if (act){
      #pragma unroll
      for (int rr=0; rr<2; rr++){
        int rl = lane*2 + rr;          // 0..63 local row
        int grow = wm + rl;            // 0..255
        int b = m0 + grow;
        float xpxh = 0.5f*g_xpx[b];
        float mloc = -1e30f, sloc = 0.f;
        #pragma unroll
        for (int c=0;c<4;c++){
          int ct = wn_i*4 + c;         // comp within tile (0..15)
          const float* Lk = sL + ct*64;
          float v[8], y[8], z[8];
          #pragma unroll
          for (int q=0;q<8;q++) v[q] = stg[rl*36 + c*8 + q] - sVmu[ct*8+q];
          #pragma unroll
          for (int ii=0;ii<8;ii++){
            float s = v[ii];
            #pragma unroll
            for (int j=0;j<ii;j++) s -= Lk[ii*8+j]*y[j];
            y[ii] = s*Lk[ii*8+ii];     // diag holds 1/L_ii
          }
          float ve = 0.f;
          #pragma unroll
          for (int ii=7;ii>=0;ii--){
            float s = y[ii];
            #pragma unroll
            for (int j=ii+1;j<8;j++) s -= Lk[j*8+ii]*z[j];
            z[ii] = s*Lk[ii*8+ii];
            ve = fmaf(v[ii], z[ii], ve);
          }
          float ll = sC2[ct] - xpxh + sMu[grow*17+ct] + 0.5f*ve;
          if (ll > mloc){ sloc = sloc*expf(mloc-ll) + 1.f; mloc = ll; }
          else            sloc += expf(ll-mloc);
        }
        sM[wn_i*256 + grow] = mloc;
        sS[wn_i*256 + grow] = sloc;
      }
    }
    __syncthreads();
  }

  if (t < 256){
    float M = sM[t], S = sS[t];
    #pragma unroll
    for (int j=1;j<4;j++){
      float mj = sM[j*256+t], sj = sS[j*256+t];
      if (mj > M){ S = S*expf(M-mj) + sj; M = mj; }
      else         S += sj*expf(mj-M);
    }
    g_pm[(size_t)blockIdx.y*BB + m0 + t] = M;
    g_ps[(size_t)blockIdx.y*BB + m0 + t] = S;
  }
}

// ---------------- merge per-tile lse partials + final mean -------------------
__global__ void k_lse(){
  int b = blockIdx.x*256 + threadIdx.x;
  float m = -1e30f, s = 0.f;
  #pragma unroll 4
  for (int tile=0; tile<NKT; tile++){
    float pm = g_pm[(size_t)tile*BB + b];
    float ps = g_ps[(size_t)tile*BB + b];
    if (pm > m){ s = s*expf(m - pm) + ps; m = pm; }
    else         s += ps*expf(pm - m);
  }
  g_nlogp[b] = -(m + logf(s));
}

__global__ void k_final(float* __restrict__ out){
  __shared__ double sh[8];
  int t = threadIdx.x;
  double acc = 0.0;
  for (int i=t;i<BB;i+=256) acc += (double)g_nlogp[i];
  #pragma unroll
  for (int o=16;o;o>>=1) acc += __shfl_down_sync(0xffffffffu, acc, o);
  if ((t&31)==0) sh[t>>5]=acc;
  __syncthreads();
  if (t==0){
    double s=0.0; for (int i=0;i<8;i++) s+=sh[i];
    out[0] = (float)(s/(double)BB);
  }
}

// ---------------- launch ------------------------------------------------------
extern "C" void kernel_launch(void* const* d_in, const int* in_sizes, int n_in,
                              void* d_out, int out_size){
  const float* x         = (const float*)d_in[0];
  const float* mu        = (const float*)d_in[1];
  const float* dir_raw   = (const float*)d_in[2];
  const float* scale_rho = (const float*)d_in[3];
  const float* psi_rho   = (const float*)d_in[4];
  const float* pi_logits = (const float*)d_in[5];

  cudaFuncSetAttribute(k_gemm, cudaFuncAttributeMaxDynamicSharedMemorySize, SMEM_DYN);

  k_psi  <<<1,256>>>(psi_rho);
  k_logpi<<<1,512>>>(pi_logits);
  k_prepx<<<BB,256>>>(x);
  k_prepk<<<KK,256>>>(mu, dir_raw, scale_rho);
  k_gemm <<<dim3(BB/BM, CC/BN),512,SMEM_DYN>>>();
  k_lse  <<<BB/256,256>>>();
  k_final<<<1,256>>>((float*)d_out);
}